// round 14
// baseline (speedup 1.0000x reference)
#include <cuda_runtime.h>
#include <cuda_fp16.h>
#include <cstdint>
#include <cstddef>

#define Bsz   64
#define Tlen  512
#define DIN   512
#define Hsz   1024
#define G4H   4096
#define NTOT  8192
#define MROWS 32768

// ---------------------------------------------------------------------------
// Persistent scratch
// G16 layout: [dir][t][slice][b][gate][16]  (slice = h/16; block per
// (dir,t,slice) = 64 b x 4 g x 16 = 4096 halves = 8 KB, contiguous)
// ---------------------------------------------------------------------------
__device__ __half   g_G16[(size_t)MROWS * NTOT];
__device__ __half   g_h_half[2][2][Bsz * Hsz];
__device__ float    g_hT[2][Bsz * Hsz];
__device__ float    g_cT[2][Bsz * Hsz];
__device__ __half   g_X_h[(size_t)MROWS * DIN];
__device__ __half   g_Wih_h[(size_t)NTOT * DIN];
__device__ __half   g_Whh_h[2][(size_t)G4H * Hsz];
__device__ unsigned g_flags[4096];

__global__ void zero_state_kernel() {
    int i = blockIdx.x * blockDim.x + threadIdx.x;
    if (i < Bsz * Hsz) {
        g_h_half[0][0][i] = __float2half(0.f);
        g_h_half[0][1][i] = __float2half(0.f);
    }
    if (i < 4096) g_flags[i] = 0u;
}

// ---------------------------------------------------------------------------
// Helpers
// ---------------------------------------------------------------------------
__device__ __forceinline__ void mma_f16(float* c, const uint32_t* a, const uint32_t* b) {
    asm volatile(
        "mma.sync.aligned.m16n8k16.row.col.f32.f16.f16.f32 "
        "{%0,%1,%2,%3},{%4,%5,%6,%7},{%8,%9},{%0,%1,%2,%3};"
        : "+f"(c[0]), "+f"(c[1]), "+f"(c[2]), "+f"(c[3])
        : "r"(a[0]), "r"(a[1]), "r"(a[2]), "r"(a[3]), "r"(b[0]), "r"(b[1]));
}
__device__ __forceinline__ void cp16(void* smem, const void* g) {
    uint32_t sa = (uint32_t)__cvta_generic_to_shared(smem);
    asm volatile("cp.async.ca.shared.global [%0], [%1], 16;" :: "r"(sa), "l"(g));
}
#define CP_COMMIT() asm volatile("cp.async.commit_group;")
#define CP_WAIT1()  asm volatile("cp.async.wait_group 1;")
#define CP_WAIT0()  asm volatile("cp.async.wait_group 0;")

__device__ __forceinline__ uint32_t smem_u32(const void* p) {
    return (uint32_t)__cvta_generic_to_shared(p);
}
__device__ __forceinline__ void mbar_init(uint32_t addr, uint32_t cnt) {
    asm volatile("mbarrier.init.shared.b64 [%0], %1;" :: "r"(addr), "r"(cnt) : "memory");
}
__device__ __forceinline__ void mbar_expect(uint32_t addr, uint32_t bytes) {
    asm volatile("mbarrier.arrive.expect_tx.shared.b64 _, [%0], %1;"
                 :: "r"(addr), "r"(bytes) : "memory");
}
__device__ __forceinline__ void mbar_arrive(uint32_t addr) {
    asm volatile("mbarrier.arrive.shared.b64 _, [%0];" :: "r"(addr) : "memory");
}
__device__ __forceinline__ void mbar_wait(uint32_t addr, uint32_t parity) {
    uint32_t done;
    do {
        asm volatile(
            "{\n\t.reg .pred p;\n\t"
            "mbarrier.try_wait.parity.acquire.cta.shared::cta.b64 p, [%1], %2, 0x989680;\n\t"
            "selp.b32 %0, 1, 0, p;\n\t}"
            : "=r"(done) : "r"(addr), "r"(parity) : "memory");
    } while (!done);
}
__device__ __forceinline__ void bulk_g2s(uint32_t dst, const void* src,
                                         uint32_t bytes, uint32_t mbar) {
    asm volatile(
        "cp.async.bulk.shared::cluster.global.mbarrier::complete_tx::bytes "
        "[%0], [%1], %2, [%3];"
        :: "r"(dst), "l"(src), "r"(bytes), "r"(mbar) : "memory");
}
#define LDSM4(r0, r1, r2, r3, addr) \
    asm volatile("ldmatrix.sync.aligned.m8n8.x4.shared.b16 {%0,%1,%2,%3}, [%4];" \
                 : "=r"(r0), "=r"(r1), "=r"(r2), "=r"(r3) : "r"(addr))
#define BAR1() asm volatile("bar.sync 1, 256;" ::: "memory")

__device__ __forceinline__ float fsig(float x) {
    return __fdividef(1.f, 1.f + __expf(-x));
}
__device__ __forceinline__ float ftanh(float x) {
    x = fminf(fmaxf(x, -15.f), 15.f);
    float t = __expf(-2.f * x);
    return __fdividef(1.f - t, 1.f + t);
}

// ---------------------------------------------------------------------------
// One-time fp16 conversion
// ---------------------------------------------------------------------------
#define NX    ((size_t)MROWS * DIN)
#define NWIH1 ((size_t)G4H * DIN)
#define NWHH1 ((size_t)G4H * Hsz)
#define NCVT  (NX + 2 * NWIH1 + 2 * NWHH1)
__global__ __launch_bounds__(256) void convert_kernel(
    const float* __restrict__ X,
    const float* __restrict__ Wihf, const float* __restrict__ Wihb,
    const float* __restrict__ Whhf, const float* __restrict__ Whhb)
{
    size_t base = ((size_t)blockIdx.x * 256 + threadIdx.x) * 8;
    const float* src;
    __half* dst;
    if (base < NX)                        { src = X + base;                         dst = g_X_h + base; }
    else if (base < NX + NWIH1)           { size_t o = base - NX;                   src = Wihf + o; dst = g_Wih_h + o; }
    else if (base < NX + 2 * NWIH1)       { size_t o = base - NX - NWIH1;           src = Wihb + o; dst = g_Wih_h + NWIH1 + o; }
    else if (base < NX + 2*NWIH1 + NWHH1) { size_t o = base - NX - 2*NWIH1;         src = Whhf + o; dst = g_Whh_h[0] + o; }
    else                                  { size_t o = base - NX - 2*NWIH1 - NWHH1; src = Whhb + o; dst = g_Whh_h[1] + o; }
    float4 v0 = ((const float4*)src)[0];
    float4 v1 = ((const float4*)src)[1];
    __half2 h0 = __floats2half2_rn(v0.x, v0.y);
    __half2 h1 = __floats2half2_rn(v0.z, v0.w);
    __half2 h2 = __floats2half2_rn(v1.x, v1.y);
    __half2 h3 = __floats2half2_rn(v1.z, v1.w);
    uint4 u;
    u.x = *(uint32_t*)&h0; u.y = *(uint32_t*)&h1;
    u.z = *(uint32_t*)&h2; u.w = *(uint32_t*)&h3;
    *(uint4*)dst = u;
}

// ---------------------------------------------------------------------------
// Phase 1: G = X @ [Wf|Wb]^T + bias  (M=32768, N=8192, K=512), fp16 MMA.
// BM=256, BN=128, BK=32, 512 threads, 3-stage ring, ldmatrix fragment loads.
// Epilogue writes the persist-friendly layout [dir][t][slice][b][g][16].
// ---------------------------------------------------------------------------
#define P1ST   40
#define P1STB  80
#define P1ASTG (256 * P1ST)
#define P1BSTG (128 * P1ST)
#define P1STG  (P1ASTG + P1BSTG)
#define P1DYN  (3 * P1STG * 2)

__global__ __launch_bounds__(512) void gemm_x_mma(
    const float* __restrict__ bihf, const float* __restrict__ bhhf,
    const float* __restrict__ bihb, const float* __restrict__ bhhb)
{
    extern __shared__ __half p1s[];
    const uint32_t smu = smem_u32(p1s);

    const int n0  = blockIdx.x * 128;
    const int m0  = blockIdx.y * 256;
    const int tid = threadIdx.x;
    const int wid = tid >> 5, lane = tid & 31;
    const int warp_m = wid & 3, warp_n = wid >> 2;
    const int groupID = lane >> 2, tig = lane & 3;

    const uint32_t lm_off = (uint32_t)((lane & 15) * P1STB + ((lane >> 4) << 4));
    const uint32_t a_warp = (uint32_t)(warp_m * 64 * P1STB);
    const uint32_t b_warp = (uint32_t)(warp_n * 32 * P1STB);

    const int iA0 = tid * 2, iA1 = tid * 2 + 1;
    const int rA0 = iA0 >> 2, uA0 = (iA0 & 3) << 3;
    const int rA1 = iA1 >> 2, uA1 = (iA1 & 3) << 3;
    const int rB  = tid >> 2, uB  = (tid & 3) << 3;
    const __half* At0 = g_X_h   + (size_t)(m0 + rA0) * DIN + uA0;
    const __half* At1 = g_X_h   + (size_t)(m0 + rA1) * DIN + uA1;
    const __half* Bt  = g_Wih_h + (size_t)(n0 + rB) * DIN + uB;

    float acc[4][4][4];
#pragma unroll
    for (int mf = 0; mf < 4; mf++)
#pragma unroll
        for (int nf = 0; nf < 4; nf++)
#pragma unroll
            for (int i = 0; i < 4; i++) acc[mf][nf][i] = 0.f;

#define P1_LOAD(st, c)                                                  \
    { int k0 = (c) * 32;                                                \
      __half* S = p1s + (st) * P1STG;                                   \
      cp16(&S[rA0 * P1ST + uA0], At0 + k0);                             \
      cp16(&S[rA1 * P1ST + uA1], At1 + k0);                             \
      cp16(&S[P1ASTG + rB * P1ST + uB], Bt + k0);                       \
      CP_COMMIT(); }

    P1_LOAD(0, 0) P1_LOAD(1, 1)
    const int NIT = DIN / 32;
    int st_c = 0, st_l = 2;
    for (int it = 0; it < NIT; it++) {
        CP_WAIT1();
        __syncthreads();
        if (it + 2 < NIT) { P1_LOAD(st_l, it + 2) }
        else              CP_COMMIT();
        if (++st_l == 3) st_l = 0;

        const uint32_t aB = smu + (uint32_t)(st_c * P1STG * 2) + a_warp + lm_off;
        const uint32_t bB = smu + (uint32_t)((st_c * P1STG + P1ASTG) * 2) + b_warp + lm_off;
        if (++st_c == 3) st_c = 0;

#pragma unroll
        for (int ks = 0; ks < 2; ks++) {
            const uint32_t kb = (uint32_t)(ks * 32);
            uint32_t av[4][4], bv[2][4];
#pragma unroll
            for (int mf = 0; mf < 4; mf++)
                LDSM4(av[mf][0], av[mf][1], av[mf][2], av[mf][3],
                      aB + (uint32_t)(mf * 16 * P1STB) + kb);
#pragma unroll
            for (int np = 0; np < 2; np++)
                LDSM4(bv[np][0], bv[np][1], bv[np][2], bv[np][3],
                      bB + (uint32_t)(np * 16 * P1STB) + kb);
#pragma unroll
            for (int mf = 0; mf < 4; mf++)
#pragma unroll
                for (int np = 0; np < 2; np++) {
                    uint32_t p0[2] = { bv[np][0], bv[np][2] };
                    uint32_t p1[2] = { bv[np][1], bv[np][3] };
                    mma_f16(acc[mf][np * 2],     av[mf], p0);
                    mma_f16(acc[mf][np * 2 + 1], av[mf], p1);
                }
        }
    }

    // Epilogue: bias + fp16 store into [dir][t][slice][b][g][16] layout.
#pragma unroll
    for (int nf = 0; nf < 4; nf++) {
        int n = n0 + warp_n * 32 + nf * 8 + 2 * tig;
        float bias0, bias1;
        if (n < G4H) { bias0 = bihf[n] + bhhf[n]; bias1 = bihf[n + 1] + bhhf[n + 1]; }
        else         { bias0 = bihb[n - G4H] + bhhb[n - G4H];
                       bias1 = bihb[n + 1 - G4H] + bhhb[n + 1 - G4H]; }
        const int dirn = n >> 12;
        const int g    = (n >> 10) & 3;
        const int sl   = (n >> 4) & 63;
        const int hp   = n & 15;
#pragma unroll
        for (int mf = 0; mf < 4; mf++) {
            int r0 = m0 + warp_m * 64 + mf * 16 + groupID;   // m = b*512 + t
            int b0 = r0 >> 9, t0 = r0 & 511;
            __half2 v0 = __floats2half2_rn(acc[mf][nf][0] + bias0, acc[mf][nf][1] + bias1);
            __half2 v1 = __floats2half2_rn(acc[mf][nf][2] + bias0, acc[mf][nf][3] + bias1);
            size_t a0 = ((((size_t)dirn * Tlen + t0) * 64 + sl) * 64 + b0) * 64 + g * 16 + hp;
            int r1 = r0 + 8;
            int b1 = r1 >> 9, t1 = r1 & 511;
            size_t a1 = ((((size_t)dirn * Tlen + t1) * 64 + sl) * 64 + b1) * 64 + g * 16 + hp;
            *(__half2*)&g_G16[a0] = v0;
            *(__half2*)&g_G16[a1] = v1;
        }
    }
}

// ---------------------------------------------------------------------------
// Phase 2: PERSISTENT LSTM (R9/R12 structure) + gate-x via single bulk DMA.
// smem: W 132,096 | h buffers 2x33,024 | Gt 64x68 f32 (17,408) | gxs 64x64 f16
// (8,192) = 223,744 B.
// ---------------------------------------------------------------------------
#define WROWB  2064
#define WBYTES (64 * WROWB)
#define HCHB   33024
#define HOFF   WBYTES
#define GTOFF  (HOFF + 2 * HCHB)
#define GXOFF  (GTOFF + 64 * 68 * 4)
#define P2DYN  (GXOFF + 64 * 64 * 2)

__global__ __launch_bounds__(288, 1) void lstm_persist(float* __restrict__ out)
{
    extern __shared__ char smraw[];
    __half* ws  = (__half*)smraw;
    float*  Gt  = (float*)(smraw + GTOFF);
    __half* gxs = (__half*)(smraw + GXOFF);
    __shared__ __align__(8) uint64_t s_mbar[6];   // F0,F1,C0,C1,G,Gc

    const uint32_t sm0  = smem_u32(smraw);
    const uint32_t hbu0 = sm0 + HOFF;
    const uint32_t hbu1 = sm0 + HOFF + HCHB;
    const uint32_t gxu  = sm0 + GXOFF;
    const uint32_t mbF0 = smem_u32(&s_mbar[0]);
    const uint32_t mbF1 = smem_u32(&s_mbar[1]);
    const uint32_t mbC0 = smem_u32(&s_mbar[2]);
    const uint32_t mbC1 = smem_u32(&s_mbar[3]);
    const uint32_t mbG  = smem_u32(&s_mbar[4]);
    const uint32_t mbGc = smem_u32(&s_mbar[5]);

    const int bid   = blockIdx.x;
    const int dir   = bid >> 6;
    const int slice = bid & 63;
    const int hb    = slice << 4;
    const int tid   = threadIdx.x;
    const int wid   = tid >> 5, lane = tid & 31;

    if (tid == 0) {
        mbar_init(mbF0, 1);   mbar_init(mbF1, 1);
        mbar_init(mbC0, 256); mbar_init(mbC1, 256);
        mbar_init(mbG, 1);    mbar_init(mbGc, 256);
    }

    if (tid < 256) {
        int r = tid >> 2, u = (tid & 3) << 3;
        int wrow = ((r >> 4) << 10) + hb + (r & 15);
        const __half* src = g_Whh_h[dir] + (size_t)wrow * Hsz;
#pragma unroll
        for (int i = 0; i < 32; i++)
            cp16(&ws[r * 1032 + u + i * 32], src + u + i * 32);
        CP_COMMIT();
        CP_WAIT0();
    }
    __syncthreads();

    if (wid < 8) {
        // =================== COMPUTE WARPS ===================
        const int grp = wid >> 1;
        const int nw  = wid & 1;
        const int groupID = lane >> 2, tig = lane & 3;

        const uint32_t a_lane  = (uint32_t)((lane & 15) * WROWB + ((lane >> 4) << 4));
        const uint32_t b_lane0 = (uint32_t)((nw * 32 + (lane & 15)) * WROWB + ((lane >> 4) << 4));
        const uint32_t kgrp_b  = (uint32_t)(grp * 512);

        const int bl = tid >> 4, j = tid & 15;

        float cv[4];
#pragma unroll
        for (int q = 0; q < 4; q++) cv[q] = 0.f;

        for (int s = 0; s < Tlen; s++) {
            const int par = s & 1;

            for (int sub = 0; sub < 4; sub++) {
                const int buf = sub & 1;
                const int f   = s * 2 + (sub >> 1);
                mbar_wait(buf ? mbF1 : mbF0, f & 1);

                float acc[4][4];
#pragma unroll
                for (int nf = 0; nf < 4; nf++)
#pragma unroll
                    for (int i = 0; i < 4; i++) acc[nf][i] = 0.f;

                const uint32_t ab = (buf ? hbu1 : hbu0) + a_lane + kgrp_b;
                const uint32_t bb = sm0 + b_lane0 + kgrp_b;
#pragma unroll
                for (int ks = 0; ks < 16; ks++) {
                    uint32_t a[4], b0r[4], b1r[4];
                    LDSM4(a[0], a[1], a[2], a[3], ab + ks * 32);
                    LDSM4(b0r[0], b0r[1], b0r[2], b0r[3], bb + ks * 32);
                    LDSM4(b1r[0], b1r[1], b1r[2], b1r[3], bb + 16 * WROWB + ks * 32);
                    uint32_t p0[2] = { b0r[0], b0r[2] }, p1[2] = { b0r[1], b0r[3] };
                    uint32_t p2[2] = { b1r[0], b1r[2] }, p3[2] = { b1r[1], b1r[3] };
                    mma_f16(acc[0], a, p0);
                    mma_f16(acc[1], a, p1);
                    mma_f16(acc[2], a, p2);
                    mma_f16(acc[3], a, p3);
                }
                mbar_arrive(buf ? mbC1 : mbC0);

#pragma unroll
                for (int nf = 0; nf < 4; nf++) {
                    int col = nw * 32 + nf * 8 + 2 * tig;
                    float* q0 = &Gt[(grp * 16 + groupID) * 68 + col];
                    float* q1 = &Gt[(grp * 16 + groupID + 8) * 68 + col];
                    q0[0] = acc[nf][0]; q0[1] = acc[nf][1];
                    q1[0] = acc[nf][2]; q1[1] = acc[nf][3];
                }
                BAR1();
                if (sub == 0) mbar_wait(mbG, s & 1);   // gx tile for step s landed

                {
                    int b = sub * 16 + bl;
                    int h = hb + j;
                    float gi = 0.f, gf = 0.f, gg = 0.f, go = 0.f;
#pragma unroll
                    for (int g4 = 0; g4 < 4; g4++) {
                        const float* gr = &Gt[(g4 * 16 + bl) * 68];
                        gi += gr[j];
                        gf += gr[16 + j];
                        gg += gr[32 + j];
                        go += gr[48 + j];
                    }
                    const __half* gx = &gxs[b * 64];
                    gi += __half2float(gx[j]);
                    gf += __half2float(gx[16 + j]);
                    gg += __half2float(gx[32 + j]);
                    go += __half2float(gx[48 + j]);

                    float si = fsig(gi);
                    float sf = fsig(gf);
                    float so = fsig(go);
                    float tg = ftanh(gg);

                    float cn = sf * cv[sub] + si * tg;
                    cv[sub] = cn;
                    float hn = so * ftanh(cn);
                    g_h_half[par ^ 1][dir][b * Hsz + h] = __float2half_rn(hn);
                    out[((size_t)b * Tlen + s) * (2 * Hsz) + dir * Hsz + h] = hn;
                    if (s == Tlen - 1) {
                        g_hT[dir][b * Hsz + h] = hn;
                        g_cT[dir][b * Hsz + h] = cn;
                    }
                }
                if (sub == 3) mbar_arrive(mbGc);       // done reading gxs this step
                BAR1();

                if (tid == 0) {
                    asm volatile("fence.proxy.async;" ::: "memory");
                    unsigned* fl = &g_flags[((dir * 4 + sub) * 64 + slice) * 8];
                    asm volatile("st.release.gpu.u32 [%0], %1;"
                                 :: "l"(fl), "r"((unsigned)(s + 1)) : "memory");
                }
            }
        }
    } else {
        // =================== PRODUCER WARP (wid == 8) ===================
        for (int s = 0; s < Tlen; s++) {
            const __half* Ht = g_h_half[s & 1][dir];
            const int t_in = dir ? (Tlen - 1 - s) : s;

            // gate-x tile: one 8 KB bulk per step
            if (lane == 0) {
                if (s > 0) mbar_wait(mbGc, (s - 1) & 1);
                mbar_expect(mbG, 8192u);
                const __half* gsrc = g_G16 +
                    (((size_t)dir * Tlen + t_in) * 64 + slice) * 4096;
                bulk_g2s(gxu, gsrc, 8192u, mbG);
            }

            for (int c = 0; c < 4; c++) {
                const int b  = c & 1;
                const int fb = s * 2 + (c >> 1);
                if (fb >= 1) mbar_wait(b ? mbC1 : mbC0, (fb - 1) & 1);
                if (s > 0) {
                    const unsigned tgt = (unsigned)s;
                    const unsigned* p0 = &g_flags[((dir * 4 + c) * 64 + lane) * 8];
                    const unsigned* p1 = &g_flags[((dir * 4 + c) * 64 + 32 + lane) * 8];
                    unsigned v0, v1;
                    do {
                        asm volatile("ld.acquire.gpu.u32 %0, [%1];" : "=r"(v0) : "l"(p0) : "memory");
                        asm volatile("ld.acquire.gpu.u32 %0, [%1];" : "=r"(v1) : "l"(p1) : "memory");
                    } while (v0 < tgt || v1 < tgt);
                    __syncwarp();
                }
                if (lane == 0) {
                    asm volatile("fence.acq_rel.gpu;" ::: "memory");
                    uint32_t mb  = b ? mbF1 : mbF0;
                    uint32_t dst = b ? hbu1 : hbu0;
                    mbar_expect(mb, 32768u);
#pragma unroll
                    for (int r = 0; r < 16; r++)
                        bulk_g2s(dst + r * WROWB, Ht + (size_t)(c * 16 + r) * Hsz, 2048u, mb);
                }
            }
        }
    }
}

// ---------------------------------------------------------------------------
// Phase 3: decoder-init projections
// ---------------------------------------------------------------------------
__global__ __launch_bounds__(128) void proj_kernel(
    const float* __restrict__ fhW, const float* __restrict__ fhb,
    const float* __restrict__ fcW, const float* __restrict__ fcb,
    float* __restrict__ out2)
{
    __shared__ float As[64][17];
    __shared__ float Bs[64][17];

    const int which = blockIdx.y;
    const float* __restrict__ W    = which ? fcW : fhW;
    const float* __restrict__ bias = which ? fcb : fhb;
    const float* __restrict__ src0 = which ? g_cT[0] : g_hT[0];
    const float* __restrict__ src1 = which ? g_cT[1] : g_hT[1];

    const int d0  = blockIdx.x * 64;
    const int tid = threadIdx.x;
    const int ty  = tid >> 4;
    const int tx  = tid & 15;

    float acc[8][4];
#pragma unroll
    for (int r = 0; r < 8; r++)
#pragma unroll
        for (int c = 0; c < 4; c++) acc[r][c] = 0.f;

    for (int k0 = 0; k0 < 2 * Hsz; k0 += 16) {
#pragma unroll
        for (int i = 0; i < 2; i++) {
            int idx = tid * 2 + i;
            int row = idx >> 2;
            int c4  = (idx & 3) << 2;
            int k   = k0 + c4;
            const float* sp = (k < Hsz) ? &src0[row * Hsz + k]
                                        : &src1[row * Hsz + k - Hsz];
            float4 v = *(const float4*)sp;
            As[row][c4 + 0] = v.x; As[row][c4 + 1] = v.y;
            As[row][c4 + 2] = v.z; As[row][c4 + 3] = v.w;

            float4 w = *(const float4*)&W[(size_t)(d0 + row) * (2 * Hsz) + k0 + c4];
            Bs[row][c4 + 0] = w.x; Bs[row][c4 + 1] = w.y;
            Bs[row][c4 + 2] = w.z; Bs[row][c4 + 3] = w.w;
        }
        __syncthreads();
#pragma unroll
        for (int kk = 0; kk < 16; kk++) {
            float a[8], b[4];
#pragma unroll
            for (int r = 0; r < 8; r++) a[r] = As[ty * 8 + r][kk];
#pragma unroll
            for (int c = 0; c < 4; c++) b[c] = Bs[tx + 16 * c][kk];
#pragma unroll
            for (int r = 0; r < 8; r++)
#pragma unroll
                for (int c = 0; c < 4; c++) acc[r][c] += a[r] * b[c];
        }
        __syncthreads();
    }

#pragma unroll
    for (int c = 0; c < 4; c++) {
        int d = d0 + tx + 16 * c;
        float bv = bias[d];
#pragma unroll
        for (int r = 0; r < 8; r++) {
            int b = ty * 8 + r;
            out2[(size_t)which * (Bsz * Hsz) + b * Hsz + d] = tanhf(acc[r][c] + bv);
        }
    }
}

// ---------------------------------------------------------------------------
// Launch
// ---------------------------------------------------------------------------
extern "C" void kernel_launch(void* const* d_in, const int* in_sizes, int n_in,
                              void* d_out, int out_size)
{
    const float* X    = (const float*)d_in[0];
    const float* Wihf = (const float*)d_in[1];
    const float* Whhf = (const float*)d_in[2];
    const float* bihf = (const float*)d_in[3];
    const float* bhhf = (const float*)d_in[4];
    const float* Wihb = (const float*)d_in[5];
    const float* Whhb = (const float*)d_in[6];
    const float* bihb = (const float*)d_in[7];
    const float* bhhb = (const float*)d_in[8];
    const float* fcW  = (const float*)d_in[9];
    const float* fcb  = (const float*)d_in[10];
    const float* fhW  = (const float*)d_in[11];
    const float* fhb  = (const float*)d_in[12];
    float* out = (float*)d_out;

    cudaFuncSetAttribute(gemm_x_mma,
                         cudaFuncAttributeMaxDynamicSharedMemorySize, P1DYN);
    cudaFuncSetAttribute(lstm_persist,
                         cudaFuncAttributeMaxDynamicSharedMemorySize, P2DYN);

    zero_state_kernel<<<(Bsz * Hsz + 255) / 256, 256>>>();

    convert_kernel<<<(unsigned)(NCVT / 8 / 256), 256>>>(X, Wihf, Wihb, Whhf, Whhb);

    gemm_x_mma<<<dim3(NTOT / 128, MROWS / 256), 512, P1DYN>>>(bihf, bhhf, bihb, bhhb);

    lstm_persist<<<128, 288, P2DYN>>>(out);

    proj_kernel<<<dim3(Hsz / 64, 2), 128>>>(
        fhW, fhb, fcW, fcb, out + (size_t)Bsz * Tlen * 2 * Hsz);
}

// round 15
// speedup vs baseline: 1.1873x; 1.1873x over previous
#include <cuda_runtime.h>
#include <cuda_fp16.h>
#include <cstdint>
#include <cstddef>

#define Bsz   64
#define Tlen  512
#define DIN   512
#define Hsz   1024
#define G4H   4096
#define NTOT  8192
#define MROWS 32768

// ---------------------------------------------------------------------------
// Persistent scratch
// ---------------------------------------------------------------------------
__device__ __half   g_G16[(size_t)MROWS * NTOT];
__device__ __half   g_h_half[2][2][Bsz * Hsz];
__device__ float    g_hT[2][Bsz * Hsz];
__device__ float    g_cT[2][Bsz * Hsz];
__device__ __half   g_X_h[(size_t)MROWS * DIN];
__device__ __half   g_Wih_h[(size_t)NTOT * DIN];
__device__ __half   g_Whh_h[2][(size_t)G4H * Hsz];
__device__ unsigned g_flags[4096];

__global__ void zero_state_kernel() {
    int i = blockIdx.x * blockDim.x + threadIdx.x;
    if (i < Bsz * Hsz) {
        g_h_half[0][0][i] = __float2half(0.f);
        g_h_half[0][1][i] = __float2half(0.f);
    }
    if (i < 4096) g_flags[i] = 0u;
}

// ---------------------------------------------------------------------------
// Helpers
// ---------------------------------------------------------------------------
__device__ __forceinline__ void mma_f16(float* c, const uint32_t* a, const uint32_t* b) {
    asm volatile(
        "mma.sync.aligned.m16n8k16.row.col.f32.f16.f16.f32 "
        "{%0,%1,%2,%3},{%4,%5,%6,%7},{%8,%9},{%0,%1,%2,%3};"
        : "+f"(c[0]), "+f"(c[1]), "+f"(c[2]), "+f"(c[3])
        : "r"(a[0]), "r"(a[1]), "r"(a[2]), "r"(a[3]), "r"(b[0]), "r"(b[1]));
}
__device__ __forceinline__ void cp16(void* smem, const void* g) {
    uint32_t sa = (uint32_t)__cvta_generic_to_shared(smem);
    asm volatile("cp.async.ca.shared.global [%0], [%1], 16;" :: "r"(sa), "l"(g));
}
#define CP_COMMIT() asm volatile("cp.async.commit_group;")
#define CP_WAIT1()  asm volatile("cp.async.wait_group 1;")
#define CP_WAIT0()  asm volatile("cp.async.wait_group 0;")

__device__ __forceinline__ uint32_t smem_u32(const void* p) {
    return (uint32_t)__cvta_generic_to_shared(p);
}
__device__ __forceinline__ void mbar_init(uint32_t addr, uint32_t cnt) {
    asm volatile("mbarrier.init.shared.b64 [%0], %1;" :: "r"(addr), "r"(cnt) : "memory");
}
__device__ __forceinline__ void mbar_expect(uint32_t addr, uint32_t bytes) {
    asm volatile("mbarrier.arrive.expect_tx.shared.b64 _, [%0], %1;"
                 :: "r"(addr), "r"(bytes) : "memory");
}
__device__ __forceinline__ void mbar_arrive(uint32_t addr) {
    asm volatile("mbarrier.arrive.shared.b64 _, [%0];" :: "r"(addr) : "memory");
}
__device__ __forceinline__ void mbar_wait(uint32_t addr, uint32_t parity) {
    uint32_t done;
    do {
        asm volatile(
            "{\n\t.reg .pred p;\n\t"
            "mbarrier.try_wait.parity.acquire.cta.shared::cta.b64 p, [%1], %2, 0x989680;\n\t"
            "selp.b32 %0, 1, 0, p;\n\t}"
            : "=r"(done) : "r"(addr), "r"(parity) : "memory");
    } while (!done);
}
__device__ __forceinline__ void bulk_g2s(uint32_t dst, const void* src,
                                         uint32_t bytes, uint32_t mbar) {
    asm volatile(
        "cp.async.bulk.shared::cluster.global.mbarrier::complete_tx::bytes "
        "[%0], [%1], %2, [%3];"
        :: "r"(dst), "l"(src), "r"(bytes), "r"(mbar) : "memory");
}
__device__ __forceinline__ void stg_cs(float* p, float v) {
    asm volatile("st.global.cs.f32 [%0], %1;" :: "l"(p), "f"(v) : "memory");
}
#define LDSM4(r0, r1, r2, r3, addr) \
    asm volatile("ldmatrix.sync.aligned.m8n8.x4.shared.b16 {%0,%1,%2,%3}, [%4];" \
                 : "=r"(r0), "=r"(r1), "=r"(r2), "=r"(r3) : "r"(addr))
#define BAR1() asm volatile("bar.sync 1, 256;" ::: "memory")

__device__ __forceinline__ float fsig(float x) {
    return __fdividef(1.f, 1.f + __expf(-x));
}
__device__ __forceinline__ float ftanh(float x) {
    x = fminf(fmaxf(x, -15.f), 15.f);
    float t = __expf(-2.f * x);
    return __fdividef(1.f - t, 1.f + t);
}

// ---------------------------------------------------------------------------
// One-time fp16 conversion
// ---------------------------------------------------------------------------
#define NX    ((size_t)MROWS * DIN)
#define NWIH1 ((size_t)G4H * DIN)
#define NWHH1 ((size_t)G4H * Hsz)
#define NCVT  (NX + 2 * NWIH1 + 2 * NWHH1)
__global__ __launch_bounds__(256) void convert_kernel(
    const float* __restrict__ X,
    const float* __restrict__ Wihf, const float* __restrict__ Wihb,
    const float* __restrict__ Whhf, const float* __restrict__ Whhb)
{
    size_t base = ((size_t)blockIdx.x * 256 + threadIdx.x) * 8;
    const float* src;
    __half* dst;
    if (base < NX)                        { src = X + base;                         dst = g_X_h + base; }
    else if (base < NX + NWIH1)           { size_t o = base - NX;                   src = Wihf + o; dst = g_Wih_h + o; }
    else if (base < NX + 2 * NWIH1)       { size_t o = base - NX - NWIH1;           src = Wihb + o; dst = g_Wih_h + NWIH1 + o; }
    else if (base < NX + 2*NWIH1 + NWHH1) { size_t o = base - NX - 2*NWIH1;         src = Whhf + o; dst = g_Whh_h[0] + o; }
    else                                  { size_t o = base - NX - 2*NWIH1 - NWHH1; src = Whhb + o; dst = g_Whh_h[1] + o; }
    float4 v0 = ((const float4*)src)[0];
    float4 v1 = ((const float4*)src)[1];
    __half2 h0 = __floats2half2_rn(v0.x, v0.y);
    __half2 h1 = __floats2half2_rn(v0.z, v0.w);
    __half2 h2 = __floats2half2_rn(v1.x, v1.y);
    __half2 h3 = __floats2half2_rn(v1.z, v1.w);
    uint4 u;
    u.x = *(uint32_t*)&h0; u.y = *(uint32_t*)&h1;
    u.z = *(uint32_t*)&h2; u.w = *(uint32_t*)&h3;
    *(uint4*)dst = u;
}

// ---------------------------------------------------------------------------
// Phase 1: G = X @ [Wf|Wb]^T + bias  (M=32768, N=8192, K=512), fp16 MMA.
// BM=256, BN=128, BK=32, 512 threads, 3-stage ring, ldmatrix fragment loads.
// ---------------------------------------------------------------------------
#define P1ST   40
#define P1STB  80
#define P1ASTG (256 * P1ST)
#define P1BSTG (128 * P1ST)
#define P1STG  (P1ASTG + P1BSTG)
#define P1DYN  (3 * P1STG * 2)

__global__ __launch_bounds__(512) void gemm_x_mma(
    const float* __restrict__ bihf, const float* __restrict__ bhhf,
    const float* __restrict__ bihb, const float* __restrict__ bhhb)
{
    extern __shared__ __half p1s[];
    const uint32_t smu = smem_u32(p1s);

    const int n0  = blockIdx.x * 128;
    const int m0  = blockIdx.y * 256;
    const int tid = threadIdx.x;
    const int wid = tid >> 5, lane = tid & 31;
    const int warp_m = wid & 3, warp_n = wid >> 2;
    const int groupID = lane >> 2, tig = lane & 3;

    const uint32_t lm_off = (uint32_t)((lane & 15) * P1STB + ((lane >> 4) << 4));
    const uint32_t a_warp = (uint32_t)(warp_m * 64 * P1STB);
    const uint32_t b_warp = (uint32_t)(warp_n * 32 * P1STB);

    const int iA0 = tid * 2, iA1 = tid * 2 + 1;
    const int rA0 = iA0 >> 2, uA0 = (iA0 & 3) << 3;
    const int rA1 = iA1 >> 2, uA1 = (iA1 & 3) << 3;
    const int rB  = tid >> 2, uB  = (tid & 3) << 3;
    const __half* At0 = g_X_h   + (size_t)(m0 + rA0) * DIN + uA0;
    const __half* At1 = g_X_h   + (size_t)(m0 + rA1) * DIN + uA1;
    const __half* Bt  = g_Wih_h + (size_t)(n0 + rB) * DIN + uB;

    float acc[4][4][4];
#pragma unroll
    for (int mf = 0; mf < 4; mf++)
#pragma unroll
        for (int nf = 0; nf < 4; nf++)
#pragma unroll
            for (int i = 0; i < 4; i++) acc[mf][nf][i] = 0.f;

#define P1_LOAD(st, c)                                                  \
    { int k0 = (c) * 32;                                                \
      __half* S = p1s + (st) * P1STG;                                   \
      cp16(&S[rA0 * P1ST + uA0], At0 + k0);                             \
      cp16(&S[rA1 * P1ST + uA1], At1 + k0);                             \
      cp16(&S[P1ASTG + rB * P1ST + uB], Bt + k0);                       \
      CP_COMMIT(); }

    P1_LOAD(0, 0) P1_LOAD(1, 1)
    const int NIT = DIN / 32;
    int st_c = 0, st_l = 2;
    for (int it = 0; it < NIT; it++) {
        CP_WAIT1();
        __syncthreads();
        if (it + 2 < NIT) { P1_LOAD(st_l, it + 2) }
        else              CP_COMMIT();
        if (++st_l == 3) st_l = 0;

        const uint32_t aB = smu + (uint32_t)(st_c * P1STG * 2) + a_warp + lm_off;
        const uint32_t bB = smu + (uint32_t)((st_c * P1STG + P1ASTG) * 2) + b_warp + lm_off;
        if (++st_c == 3) st_c = 0;

#pragma unroll
        for (int ks = 0; ks < 2; ks++) {
            const uint32_t kb = (uint32_t)(ks * 32);
            uint32_t av[4][4], bv[2][4];
#pragma unroll
            for (int mf = 0; mf < 4; mf++)
                LDSM4(av[mf][0], av[mf][1], av[mf][2], av[mf][3],
                      aB + (uint32_t)(mf * 16 * P1STB) + kb);
#pragma unroll
            for (int np = 0; np < 2; np++)
                LDSM4(bv[np][0], bv[np][1], bv[np][2], bv[np][3],
                      bB + (uint32_t)(np * 16 * P1STB) + kb);
#pragma unroll
            for (int mf = 0; mf < 4; mf++)
#pragma unroll
                for (int np = 0; np < 2; np++) {
                    uint32_t p0[2] = { bv[np][0], bv[np][2] };
                    uint32_t p1[2] = { bv[np][1], bv[np][3] };
                    mma_f16(acc[mf][np * 2],     av[mf], p0);
                    mma_f16(acc[mf][np * 2 + 1], av[mf], p1);
                }
        }
    }

#pragma unroll
    for (int nf = 0; nf < 4; nf++) {
        int c0 = warp_n * 32 + nf * 8 + 2 * tig;
        int n  = n0 + c0;
        float bias0, bias1;
        if (n < G4H) { bias0 = bihf[n] + bhhf[n]; bias1 = bihf[n + 1] + bhhf[n + 1]; }
        else         { bias0 = bihb[n - G4H] + bhhb[n - G4H];
                       bias1 = bihb[n + 1 - G4H] + bhhb[n + 1 - G4H]; }
#pragma unroll
        for (int mf = 0; mf < 4; mf++) {
            int r0 = m0 + warp_m * 64 + mf * 16 + groupID;
            __half2 v0 = __floats2half2_rn(acc[mf][nf][0] + bias0, acc[mf][nf][1] + bias1);
            __half2 v1 = __floats2half2_rn(acc[mf][nf][2] + bias0, acc[mf][nf][3] + bias1);
            *(__half2*)&g_G16[(size_t)r0 * NTOT + n]       = v0;
            *(__half2*)&g_G16[(size_t)(r0 + 8) * NTOT + n] = v1;
        }
    }
}

// ---------------------------------------------------------------------------
// Phase 2: PERSISTENT LSTM (R13 proven layout): bulk-DMA producer warp +
// all-8-warps-per-chunk K-split GEMM + flag-gated dataflow.
// ---------------------------------------------------------------------------
#define WROWB  2064
#define WBYTES (64 * WROWB)
#define HCHB   33024
#define HOFF   WBYTES
#define GTOFF  (HOFF + 2 * HCHB)
#define GXOFF  (GTOFF + 4 * 16 * 68 * 4)
#define P2DYN  (GXOFF + 64 * 72 * 2)

__global__ __launch_bounds__(288, 1) void lstm_persist(float* __restrict__ out)
{
    extern __shared__ char smraw[];
    __half* ws  = (__half*)smraw;
    float*  Gt  = (float*)(smraw + GTOFF);
    __half* gxs = (__half*)(smraw + GXOFF);
    __shared__ __align__(8) uint64_t s_mbar[4];

    const uint32_t sm0  = smem_u32(smraw);
    const uint32_t hbu0 = sm0 + HOFF;
    const uint32_t hbu1 = sm0 + HOFF + HCHB;
    const uint32_t mbF0 = smem_u32(&s_mbar[0]);
    const uint32_t mbF1 = smem_u32(&s_mbar[1]);
    const uint32_t mbC0 = smem_u32(&s_mbar[2]);
    const uint32_t mbC1 = smem_u32(&s_mbar[3]);

    const int bid   = blockIdx.x;
    const int dir   = bid >> 6;
    const int slice = bid & 63;
    const int hb    = slice << 4;
    const int tid   = threadIdx.x;
    const int wid   = tid >> 5, lane = tid & 31;

    if (tid == 0) {
        mbar_init(mbF0, 1);   mbar_init(mbF1, 1);
        mbar_init(mbC0, 256); mbar_init(mbC1, 256);
    }

    if (tid < 256) {
        int r = tid >> 2, u = (tid & 3) << 3;
        int wrow = ((r >> 4) << 10) + hb + (r & 15);
        const __half* src = g_Whh_h[dir] + (size_t)wrow * Hsz;
#pragma unroll
        for (int i = 0; i < 32; i++)
            cp16(&ws[r * 1032 + u + i * 32], src + u + i * 32);
        CP_COMMIT();
        CP_WAIT0();
    }
    __syncthreads();

    if (wid < 8) {
        const int grp = wid >> 1;
        const int nw  = wid & 1;
        const int groupID = lane >> 2, tig = lane & 3;

        const uint32_t a_lane  = (uint32_t)((lane & 15) * WROWB + ((lane >> 4) << 4));
        const uint32_t b_lane0 = (uint32_t)((nw * 32 + (lane & 15)) * WROWB + ((lane >> 4) << 4));
        const uint32_t kgrp_b  = (uint32_t)(grp * 512);

        const int o0 = tid * 2, o1 = tid * 2 + 1;
        const int bl = tid >> 4, j = tid & 15;

        float cv[4];
#pragma unroll
        for (int q = 0; q < 4; q++) cv[q] = 0.f;

        for (int s = 0; s < Tlen; s++) {
            const int par  = s & 1;
            const int t_in = dir ? (Tlen - 1 - s) : s;

            {
                int b0 = o0 >> 3, g0 = (o0 >> 1) & 3, f0 = o0 & 1;
                int b1 = o1 >> 3, g1 = (o1 >> 1) & 3, f1 = o1 & 1;
                cp16(&gxs[b0 * 72 + g0 * 16 + f0 * 8],
                     g_G16 + ((size_t)b0 * Tlen + t_in) * NTOT + dir * G4H + g0 * 1024 + hb + f0 * 8);
                cp16(&gxs[b1 * 72 + g1 * 16 + f1 * 8],
                     g_G16 + ((size_t)b1 * Tlen + t_in) * NTOT + dir * G4H + g1 * 1024 + hb + f1 * 8);
                CP_COMMIT();
            }

            for (int sub = 0; sub < 4; sub++) {
                const int buf = sub & 1;
                const int f   = s * 2 + (sub >> 1);
                mbar_wait(buf ? mbF1 : mbF0, f & 1);

                float acc[4][4];
#pragma unroll
                for (int nf = 0; nf < 4; nf++)
#pragma unroll
                    for (int i = 0; i < 4; i++) acc[nf][i] = 0.f;

                const uint32_t ab = (buf ? hbu1 : hbu0) + a_lane + kgrp_b;
                const uint32_t bb = sm0 + b_lane0 + kgrp_b;
#pragma unroll
                for (int ks = 0; ks < 16; ks++) {
                    uint32_t a[4], b0r[4], b1r[4];
                    LDSM4(a[0], a[1], a[2], a[3], ab + ks * 32);
                    LDSM4(b0r[0], b0r[1], b0r[2], b0r[3], bb + ks * 32);
                    LDSM4(b1r[0], b1r[1], b1r[2], b1r[3], bb + 16 * WROWB + ks * 32);
                    uint32_t p0[2] = { b0r[0], b0r[2] }, p1[2] = { b0r[1], b0r[3] };
                    uint32_t p2[2] = { b1r[0], b1r[2] }, p3[2] = { b1r[1], b1r[3] };
                    mma_f16(acc[0], a, p0);
                    mma_f16(acc[1], a, p1);
                    mma_f16(acc[2], a, p2);
                    mma_f16(acc[3], a, p3);
                }
                mbar_arrive(buf ? mbC1 : mbC0);

#pragma unroll
                for (int nf = 0; nf < 4; nf++) {
                    int col = nw * 32 + nf * 8 + 2 * tig;
                    float* q0 = &Gt[(grp * 16 + groupID) * 68 + col];
                    float* q1 = &Gt[(grp * 16 + groupID + 8) * 68 + col];
                    q0[0] = acc[nf][0]; q0[1] = acc[nf][1];
                    q1[0] = acc[nf][2]; q1[1] = acc[nf][3];
                }
                if (sub == 0) CP_WAIT0();
                BAR1();

                {
                    int b = sub * 16 + bl;
                    int h = hb + j;
                    float gi = 0.f, gf = 0.f, gg = 0.f, go = 0.f;
#pragma unroll
                    for (int g4 = 0; g4 < 4; g4++) {
                        const float* gr = &Gt[(g4 * 16 + bl) * 68];
                        gi += gr[j];
                        gf += gr[16 + j];
                        gg += gr[32 + j];
                        go += gr[48 + j];
                    }
                    const __half* gx = &gxs[b * 72];
                    gi += __half2float(gx[j]);
                    gf += __half2float(gx[16 + j]);
                    gg += __half2float(gx[32 + j]);
                    go += __half2float(gx[48 + j]);

                    float si = fsig(gi);
                    float sf = fsig(gf);
                    float so = fsig(go);
                    float tg = ftanh(gg);

                    float cn = sf * cv[sub] + si * tg;
                    cv[sub] = cn;
                    float hn = so * ftanh(cn);
                    g_h_half[par ^ 1][dir][b * Hsz + h] = __float2half_rn(hn);
                    stg_cs(&out[((size_t)b * Tlen + s) * (2 * Hsz) + dir * Hsz + h], hn);
                    if (s == Tlen - 1) {
                        g_hT[dir][b * Hsz + h] = hn;
                        g_cT[dir][b * Hsz + h] = cn;
                    }
                }
                BAR1();

                if (tid == 0) {
                    unsigned* fl = &g_flags[((dir * 4 + sub) * 64 + slice) * 8];
                    asm volatile("st.release.gpu.u32 [%0], %1;"
                                 :: "l"(fl), "r"((unsigned)(s + 1)) : "memory");
                }
            }
        }
    } else {
        for (int s = 0; s < Tlen; s++) {
            const __half* Ht = g_h_half[s & 1][dir];
            for (int c = 0; c < 4; c++) {
                const int b  = c & 1;
                const int fb = s * 2 + (c >> 1);
                if (fb >= 1) mbar_wait(b ? mbC1 : mbC0, (fb - 1) & 1);
                if (s > 0) {
                    const unsigned tgt = (unsigned)s;
                    const unsigned* p0 = &g_flags[((dir * 4 + c) * 64 + lane) * 8];
                    const unsigned* p1 = &g_flags[((dir * 4 + c) * 64 + 32 + lane) * 8];
                    unsigned v0, v1;
                    do {
                        asm volatile("ld.acquire.gpu.u32 %0, [%1];" : "=r"(v0) : "l"(p0) : "memory");
                        asm volatile("ld.acquire.gpu.u32 %0, [%1];" : "=r"(v1) : "l"(p1) : "memory");
                    } while (v0 < tgt || v1 < tgt);
                    __syncwarp();
                }
                if (lane == 0) {
                    asm volatile("fence.acq_rel.gpu;" ::: "memory");
                    uint32_t mb  = b ? mbF1 : mbF0;
                    uint32_t dst = b ? hbu1 : hbu0;
                    mbar_expect(mb, 32768u);
#pragma unroll
                    for (int r = 0; r < 16; r++)
                        bulk_g2s(dst + r * WROWB, Ht + (size_t)(c * 16 + r) * Hsz, 2048u, mb);
                }
            }
        }
    }
}

// ---------------------------------------------------------------------------
// Phase 3: decoder-init projections
// ---------------------------------------------------------------------------
__global__ __launch_bounds__(128) void proj_kernel(
    const float* __restrict__ fhW, const float* __restrict__ fhb,
    const float* __restrict__ fcW, const float* __restrict__ fcb,
    float* __restrict__ out2)
{
    __shared__ float As[64][17];
    __shared__ float Bs[64][17];

    const int which = blockIdx.y;
    const float* __restrict__ W    = which ? fcW : fhW;
    const float* __restrict__ bias = which ? fcb : fhb;
    const float* __restrict__ src0 = which ? g_cT[0] : g_hT[0];
    const float* __restrict__ src1 = which ? g_cT[1] : g_hT[1];

    const int d0  = blockIdx.x * 64;
    const int tid = threadIdx.x;
    const int ty  = tid >> 4;
    const int tx  = tid & 15;

    float acc[8][4];
#pragma unroll
    for (int r = 0; r < 8; r++)
#pragma unroll
        for (int c = 0; c < 4; c++) acc[r][c] = 0.f;

    for (int k0 = 0; k0 < 2 * Hsz; k0 += 16) {
#pragma unroll
        for (int i = 0; i < 2; i++) {
            int idx = tid * 2 + i;
            int row = idx >> 2;
            int c4  = (idx & 3) << 2;
            int k   = k0 + c4;
            const float* sp = (k < Hsz) ? &src0[row * Hsz + k]
                                        : &src1[row * Hsz + k - Hsz];
            float4 v = *(const float4*)sp;
            As[row][c4 + 0] = v.x; As[row][c4 + 1] = v.y;
            As[row][c4 + 2] = v.z; As[row][c4 + 3] = v.w;

            float4 w = *(const float4*)&W[(size_t)(d0 + row) * (2 * Hsz) + k0 + c4];
            Bs[row][c4 + 0] = w.x; Bs[row][c4 + 1] = w.y;
            Bs[row][c4 + 2] = w.z; Bs[row][c4 + 3] = w.w;
        }
        __syncthreads();
#pragma unroll
        for (int kk = 0; kk < 16; kk++) {
            float a[8], b[4];
#pragma unroll
            for (int r = 0; r < 8; r++) a[r] = As[ty * 8 + r][kk];
#pragma unroll
            for (int c = 0; c < 4; c++) b[c] = Bs[tx + 16 * c][kk];
#pragma unroll
            for (int r = 0; r < 8; r++)
#pragma unroll
                for (int c = 0; c < 4; c++) acc[r][c] += a[r] * b[c];
        }
        __syncthreads();
    }

#pragma unroll
    for (int c = 0; c < 4; c++) {
        int d = d0 + tx + 16 * c;
        float bv = bias[d];
#pragma unroll
        for (int r = 0; r < 8; r++) {
            int b = ty * 8 + r;
            out2[(size_t)which * (Bsz * Hsz) + b * Hsz + d] = tanhf(acc[r][c] + bv);
        }
    }
}

// ---------------------------------------------------------------------------
// Launch
// ---------------------------------------------------------------------------
extern "C" void kernel_launch(void* const* d_in, const int* in_sizes, int n_in,
                              void* d_out, int out_size)
{
    const float* X    = (const float*)d_in[0];
    const float* Wihf = (const float*)d_in[1];
    const float* Whhf = (const float*)d_in[2];
    const float* bihf = (const float*)d_in[3];
    const float* bhhf = (const float*)d_in[4];
    const float* Wihb = (const float*)d_in[5];
    const float* Whhb = (const float*)d_in[6];
    const float* bihb = (const float*)d_in[7];
    const float* bhhb = (const float*)d_in[8];
    const float* fcW  = (const float*)d_in[9];
    const float* fcb  = (const float*)d_in[10];
    const float* fhW  = (const float*)d_in[11];
    const float* fhb  = (const float*)d_in[12];
    float* out = (float*)d_out;

    cudaFuncSetAttribute(gemm_x_mma,
                         cudaFuncAttributeMaxDynamicSharedMemorySize, P1DYN);
    cudaFuncSetAttribute(lstm_persist,
                         cudaFuncAttributeMaxDynamicSharedMemorySize, P2DYN);

    zero_state_kernel<<<(Bsz * Hsz + 255) / 256, 256>>>();

    convert_kernel<<<(unsigned)(NCVT / 8 / 256), 256>>>(X, Wihf, Wihb, Whhf, Whhb);

    gemm_x_mma<<<dim3(NTOT / 128, MROWS / 256), 512, P1DYN>>>(bihf, bhhf, bihb, bhhb);

    lstm_persist<<<128, 288, P2DYN>>>(out);

    proj_kernel<<<dim3(Hsz / 64, 2), 128>>>(
        fhW, fhb, fcW, fcb, out + (size_t)Bsz * Tlen * 2 * Hsz);
}

// round 16
// speedup vs baseline: 1.2151x; 1.0234x over previous
#include <cuda_runtime.h>
#include <cuda_fp16.h>
#include <cstdint>
#include <cstddef>

#define Bsz   64
#define Tlen  512
#define DIN   512
#define Hsz   1024
#define G4H   4096
#define NTOT  8192
#define MROWS 32768

// ---------------------------------------------------------------------------
// Persistent scratch
// ---------------------------------------------------------------------------
__device__ __half   g_G16[(size_t)MROWS * NTOT];
__device__ __half   g_h_half[2][2][Bsz * Hsz];
__device__ float    g_hT[2][Bsz * Hsz];
__device__ float    g_cT[2][Bsz * Hsz];
__device__ __half   g_X_h[(size_t)MROWS * DIN];
__device__ __half   g_Wih_h[(size_t)NTOT * DIN];
__device__ __half   g_Whh_h[2][(size_t)G4H * Hsz];
__device__ unsigned g_flags[4096];

// ---------------------------------------------------------------------------
// Helpers
// ---------------------------------------------------------------------------
__device__ __forceinline__ void mma_f16(float* c, const uint32_t* a, const uint32_t* b) {
    asm volatile(
        "mma.sync.aligned.m16n8k16.row.col.f32.f16.f16.f32 "
        "{%0,%1,%2,%3},{%4,%5,%6,%7},{%8,%9},{%0,%1,%2,%3};"
        : "+f"(c[0]), "+f"(c[1]), "+f"(c[2]), "+f"(c[3])
        : "r"(a[0]), "r"(a[1]), "r"(a[2]), "r"(a[3]), "r"(b[0]), "r"(b[1]));
}
__device__ __forceinline__ void cp16(void* smem, const void* g) {
    uint32_t sa = (uint32_t)__cvta_generic_to_shared(smem);
    asm volatile("cp.async.ca.shared.global [%0], [%1], 16;" :: "r"(sa), "l"(g));
}
#define CP_COMMIT() asm volatile("cp.async.commit_group;")
#define CP_WAIT1()  asm volatile("cp.async.wait_group 1;")
#define CP_WAIT0()  asm volatile("cp.async.wait_group 0;")

__device__ __forceinline__ uint32_t smem_u32(const void* p) {
    return (uint32_t)__cvta_generic_to_shared(p);
}
__device__ __forceinline__ void mbar_init(uint32_t addr, uint32_t cnt) {
    asm volatile("mbarrier.init.shared.b64 [%0], %1;" :: "r"(addr), "r"(cnt) : "memory");
}
__device__ __forceinline__ void mbar_expect(uint32_t addr, uint32_t bytes) {
    asm volatile("mbarrier.arrive.expect_tx.shared.b64 _, [%0], %1;"
                 :: "r"(addr), "r"(bytes) : "memory");
}
__device__ __forceinline__ void mbar_arrive(uint32_t addr) {
    asm volatile("mbarrier.arrive.shared.b64 _, [%0];" :: "r"(addr) : "memory");
}
__device__ __forceinline__ void mbar_wait(uint32_t addr, uint32_t parity) {
    uint32_t done;
    do {
        asm volatile(
            "{\n\t.reg .pred p;\n\t"
            "mbarrier.try_wait.parity.acquire.cta.shared::cta.b64 p, [%1], %2, 0x989680;\n\t"
            "selp.b32 %0, 1, 0, p;\n\t}"
            : "=r"(done) : "r"(addr), "r"(parity) : "memory");
    } while (!done);
}
__device__ __forceinline__ void bulk_g2s(uint32_t dst, const void* src,
                                         uint32_t bytes, uint32_t mbar) {
    asm volatile(
        "cp.async.bulk.shared::cluster.global.mbarrier::complete_tx::bytes "
        "[%0], [%1], %2, [%3];"
        :: "r"(dst), "l"(src), "r"(bytes), "r"(mbar) : "memory");
}
#define LDSM4(r0, r1, r2, r3, addr) \
    asm volatile("ldmatrix.sync.aligned.m8n8.x4.shared.b16 {%0,%1,%2,%3}, [%4];" \
                 : "=r"(r0), "=r"(r1), "=r"(r2), "=r"(r3) : "r"(addr))
#define BAR1() asm volatile("bar.sync 1, 256;" ::: "memory")

__device__ __forceinline__ float fsig(float x) {
    return __fdividef(1.f, 1.f + __expf(-x));
}
__device__ __forceinline__ float ftanh(float x) {
    x = fminf(fmaxf(x, -15.f), 15.f);
    float t = __expf(-2.f * x);
    return __fdividef(1.f - t, 1.f + t);
}

// ---------------------------------------------------------------------------
// One-time fp16 conversion + state zeroing (fused; convert precedes all users)
// ---------------------------------------------------------------------------
#define NX    ((size_t)MROWS * DIN)
#define NWIH1 ((size_t)G4H * DIN)
#define NWHH1 ((size_t)G4H * Hsz)
#define NCVT  (NX + 2 * NWIH1 + 2 * NWHH1)
__global__ __launch_bounds__(256) void convert_kernel(
    const float* __restrict__ X,
    const float* __restrict__ Wihf, const float* __restrict__ Wihb,
    const float* __restrict__ Whhf, const float* __restrict__ Whhb)
{
    int gt = blockIdx.x * 256 + threadIdx.x;
    // fused zero-state: first 65536 threads clear h, first 4096 clear flags
    if (gt < Bsz * Hsz) {
        g_h_half[0][0][gt] = __float2half(0.f);
        g_h_half[0][1][gt] = __float2half(0.f);
    }
    if (gt < 4096) g_flags[gt] = 0u;

    size_t base = (size_t)gt * 8;
    if (base >= NCVT) return;
    const float* src;
    __half* dst;
    if (base < NX)                        { src = X + base;                         dst = g_X_h + base; }
    else if (base < NX + NWIH1)           { size_t o = base - NX;                   src = Wihf + o; dst = g_Wih_h + o; }
    else if (base < NX + 2 * NWIH1)       { size_t o = base - NX - NWIH1;           src = Wihb + o; dst = g_Wih_h + NWIH1 + o; }
    else if (base < NX + 2*NWIH1 + NWHH1) { size_t o = base - NX - 2*NWIH1;         src = Whhf + o; dst = g_Whh_h[0] + o; }
    else                                  { size_t o = base - NX - 2*NWIH1 - NWHH1; src = Whhb + o; dst = g_Whh_h[1] + o; }
    float4 v0 = ((const float4*)src)[0];
    float4 v1 = ((const float4*)src)[1];
    __half2 h0 = __floats2half2_rn(v0.x, v0.y);
    __half2 h1 = __floats2half2_rn(v0.z, v0.w);
    __half2 h2 = __floats2half2_rn(v1.x, v1.y);
    __half2 h3 = __floats2half2_rn(v1.z, v1.w);
    uint4 u;
    u.x = *(uint32_t*)&h0; u.y = *(uint32_t*)&h1;
    u.z = *(uint32_t*)&h2; u.w = *(uint32_t*)&h3;
    *(uint4*)dst = u;
}

// ---------------------------------------------------------------------------
// Phase 1: G = X @ [Wf|Wb]^T + bias  (M=32768, N=8192, K=512), fp16 MMA.
// BM=256, BN=128, BK=32, 512 threads, 3-stage ring, ldmatrix fragment loads.
// ---------------------------------------------------------------------------
#define P1ST   40
#define P1STB  80
#define P1ASTG (256 * P1ST)
#define P1BSTG (128 * P1ST)
#define P1STG  (P1ASTG + P1BSTG)
#define P1DYN  (3 * P1STG * 2)

__global__ __launch_bounds__(512) void gemm_x_mma(
    const float* __restrict__ bihf, const float* __restrict__ bhhf,
    const float* __restrict__ bihb, const float* __restrict__ bhhb)
{
    extern __shared__ __half p1s[];
    const uint32_t smu = smem_u32(p1s);

    const int n0  = blockIdx.x * 128;
    const int m0  = blockIdx.y * 256;
    const int tid = threadIdx.x;
    const int wid = tid >> 5, lane = tid & 31;
    const int warp_m = wid & 3, warp_n = wid >> 2;
    const int groupID = lane >> 2, tig = lane & 3;

    const uint32_t lm_off = (uint32_t)((lane & 15) * P1STB + ((lane >> 4) << 4));
    const uint32_t a_warp = (uint32_t)(warp_m * 64 * P1STB);
    const uint32_t b_warp = (uint32_t)(warp_n * 32 * P1STB);

    const int iA0 = tid * 2, iA1 = tid * 2 + 1;
    const int rA0 = iA0 >> 2, uA0 = (iA0 & 3) << 3;
    const int rA1 = iA1 >> 2, uA1 = (iA1 & 3) << 3;
    const int rB  = tid >> 2, uB  = (tid & 3) << 3;
    const __half* At0 = g_X_h   + (size_t)(m0 + rA0) * DIN + uA0;
    const __half* At1 = g_X_h   + (size_t)(m0 + rA1) * DIN + uA1;
    const __half* Bt  = g_Wih_h + (size_t)(n0 + rB) * DIN + uB;

    float acc[4][4][4];
#pragma unroll
    for (int mf = 0; mf < 4; mf++)
#pragma unroll
        for (int nf = 0; nf < 4; nf++)
#pragma unroll
            for (int i = 0; i < 4; i++) acc[mf][nf][i] = 0.f;

#define P1_LOAD(st, c)                                                  \
    { int k0 = (c) * 32;                                                \
      __half* S = p1s + (st) * P1STG;                                   \
      cp16(&S[rA0 * P1ST + uA0], At0 + k0);                             \
      cp16(&S[rA1 * P1ST + uA1], At1 + k0);                             \
      cp16(&S[P1ASTG + rB * P1ST + uB], Bt + k0);                       \
      CP_COMMIT(); }

    P1_LOAD(0, 0) P1_LOAD(1, 1)
    const int NIT = DIN / 32;
    int st_c = 0, st_l = 2;
    for (int it = 0; it < NIT; it++) {
        CP_WAIT1();
        __syncthreads();
        if (it + 2 < NIT) { P1_LOAD(st_l, it + 2) }
        else              CP_COMMIT();
        if (++st_l == 3) st_l = 0;

        const uint32_t aB = smu + (uint32_t)(st_c * P1STG * 2) + a_warp + lm_off;
        const uint32_t bB = smu + (uint32_t)((st_c * P1STG + P1ASTG) * 2) + b_warp + lm_off;
        if (++st_c == 3) st_c = 0;

#pragma unroll
        for (int ks = 0; ks < 2; ks++) {
            const uint32_t kb = (uint32_t)(ks * 32);
            uint32_t av[4][4], bv[2][4];
#pragma unroll
            for (int mf = 0; mf < 4; mf++)
                LDSM4(av[mf][0], av[mf][1], av[mf][2], av[mf][3],
                      aB + (uint32_t)(mf * 16 * P1STB) + kb);
#pragma unroll
            for (int np = 0; np < 2; np++)
                LDSM4(bv[np][0], bv[np][1], bv[np][2], bv[np][3],
                      bB + (uint32_t)(np * 16 * P1STB) + kb);
#pragma unroll
            for (int mf = 0; mf < 4; mf++)
#pragma unroll
                for (int np = 0; np < 2; np++) {
                    uint32_t p0[2] = { bv[np][0], bv[np][2] };
                    uint32_t p1[2] = { bv[np][1], bv[np][3] };
                    mma_f16(acc[mf][np * 2],     av[mf], p0);
                    mma_f16(acc[mf][np * 2 + 1], av[mf], p1);
                }
        }
    }

#pragma unroll
    for (int nf = 0; nf < 4; nf++) {
        int c0 = warp_n * 32 + nf * 8 + 2 * tig;
        int n  = n0 + c0;
        float bias0, bias1;
        if (n < G4H) { bias0 = bihf[n] + bhhf[n]; bias1 = bihf[n + 1] + bhhf[n + 1]; }
        else         { bias0 = bihb[n - G4H] + bhhb[n - G4H];
                       bias1 = bihb[n + 1 - G4H] + bhhb[n + 1 - G4H]; }
#pragma unroll
        for (int mf = 0; mf < 4; mf++) {
            int r0 = m0 + warp_m * 64 + mf * 16 + groupID;
            __half2 v0 = __floats2half2_rn(acc[mf][nf][0] + bias0, acc[mf][nf][1] + bias1);
            __half2 v1 = __floats2half2_rn(acc[mf][nf][2] + bias0, acc[mf][nf][3] + bias1);
            *(__half2*)&g_G16[(size_t)r0 * NTOT + n]       = v0;
            *(__half2*)&g_G16[(size_t)(r0 + 8) * NTOT + n] = v1;
        }
    }
}

// ---------------------------------------------------------------------------
// Phase 2: PERSISTENT LSTM (R13 proven layout): bulk-DMA producer warp +
// all-8-warps-per-chunk K-split GEMM + flag-gated dataflow.
// ---------------------------------------------------------------------------
#define WROWB  2064
#define WBYTES (64 * WROWB)
#define HCHB   33024
#define HOFF   WBYTES
#define GTOFF  (HOFF + 2 * HCHB)
#define GXOFF  (GTOFF + 4 * 16 * 68 * 4)
#define P2DYN  (GXOFF + 64 * 72 * 2)

__global__ __launch_bounds__(288, 1) void lstm_persist(float* __restrict__ out)
{
    extern __shared__ char smraw[];
    __half* ws  = (__half*)smraw;
    float*  Gt  = (float*)(smraw + GTOFF);
    __half* gxs = (__half*)(smraw + GXOFF);
    __shared__ __align__(8) uint64_t s_mbar[4];

    const uint32_t sm0  = smem_u32(smraw);
    const uint32_t hbu0 = sm0 + HOFF;
    const uint32_t hbu1 = sm0 + HOFF + HCHB;
    const uint32_t mbF0 = smem_u32(&s_mbar[0]);
    const uint32_t mbF1 = smem_u32(&s_mbar[1]);
    const uint32_t mbC0 = smem_u32(&s_mbar[2]);
    const uint32_t mbC1 = smem_u32(&s_mbar[3]);

    const int bid   = blockIdx.x;
    const int dir   = bid >> 6;
    const int slice = bid & 63;
    const int hb    = slice << 4;
    const int tid   = threadIdx.x;
    const int wid   = tid >> 5, lane = tid & 31;

    if (tid == 0) {
        mbar_init(mbF0, 1);   mbar_init(mbF1, 1);
        mbar_init(mbC0, 256); mbar_init(mbC1, 256);
    }

    if (tid < 256) {
        int r = tid >> 2, u = (tid & 3) << 3;
        int wrow = ((r >> 4) << 10) + hb + (r & 15);
        const __half* src = g_Whh_h[dir] + (size_t)wrow * Hsz;
#pragma unroll
        for (int i = 0; i < 32; i++)
            cp16(&ws[r * 1032 + u + i * 32], src + u + i * 32);
        CP_COMMIT();
        CP_WAIT0();
    }
    __syncthreads();

    if (wid < 8) {
        const int grp = wid >> 1;
        const int nw  = wid & 1;
        const int groupID = lane >> 2, tig = lane & 3;

        const uint32_t a_lane  = (uint32_t)((lane & 15) * WROWB + ((lane >> 4) << 4));
        const uint32_t b_lane0 = (uint32_t)((nw * 32 + (lane & 15)) * WROWB + ((lane >> 4) << 4));
        const uint32_t kgrp_b  = (uint32_t)(grp * 512);

        const int o0 = tid * 2, o1 = tid * 2 + 1;
        const int bl = tid >> 4, j = tid & 15;

        float cv[4];
#pragma unroll
        for (int q = 0; q < 4; q++) cv[q] = 0.f;

        for (int s = 0; s < Tlen; s++) {
            const int par  = s & 1;
            const int t_in = dir ? (Tlen - 1 - s) : s;

            {
                int b0 = o0 >> 3, g0 = (o0 >> 1) & 3, f0 = o0 & 1;
                int b1 = o1 >> 3, g1 = (o1 >> 1) & 3, f1 = o1 & 1;
                cp16(&gxs[b0 * 72 + g0 * 16 + f0 * 8],
                     g_G16 + ((size_t)b0 * Tlen + t_in) * NTOT + dir * G4H + g0 * 1024 + hb + f0 * 8);
                cp16(&gxs[b1 * 72 + g1 * 16 + f1 * 8],
                     g_G16 + ((size_t)b1 * Tlen + t_in) * NTOT + dir * G4H + g1 * 1024 + hb + f1 * 8);
                CP_COMMIT();
            }

            for (int sub = 0; sub < 4; sub++) {
                const int buf = sub & 1;
                const int f   = s * 2 + (sub >> 1);
                mbar_wait(buf ? mbF1 : mbF0, f & 1);

                float acc[4][4];
#pragma unroll
                for (int nf = 0; nf < 4; nf++)
#pragma unroll
                    for (int i = 0; i < 4; i++) acc[nf][i] = 0.f;

                const uint32_t ab = (buf ? hbu1 : hbu0) + a_lane + kgrp_b;
                const uint32_t bb = sm0 + b_lane0 + kgrp_b;
#pragma unroll
                for (int ks = 0; ks < 16; ks++) {
                    uint32_t a[4], b0r[4], b1r[4];
                    LDSM4(a[0], a[1], a[2], a[3], ab + ks * 32);
                    LDSM4(b0r[0], b0r[1], b0r[2], b0r[3], bb + ks * 32);
                    LDSM4(b1r[0], b1r[1], b1r[2], b1r[3], bb + 16 * WROWB + ks * 32);
                    uint32_t p0[2] = { b0r[0], b0r[2] }, p1[2] = { b0r[1], b0r[3] };
                    uint32_t p2[2] = { b1r[0], b1r[2] }, p3[2] = { b1r[1], b1r[3] };
                    mma_f16(acc[0], a, p0);
                    mma_f16(acc[1], a, p1);
                    mma_f16(acc[2], a, p2);
                    mma_f16(acc[3], a, p3);
                }
                mbar_arrive(buf ? mbC1 : mbC0);

#pragma unroll
                for (int nf = 0; nf < 4; nf++) {
                    int col = nw * 32 + nf * 8 + 2 * tig;
                    float* q0 = &Gt[(grp * 16 + groupID) * 68 + col];
                    float* q1 = &Gt[(grp * 16 + groupID + 8) * 68 + col];
                    q0[0] = acc[nf][0]; q0[1] = acc[nf][1];
                    q1[0] = acc[nf][2]; q1[1] = acc[nf][3];
                }
                if (sub == 0) CP_WAIT0();
                BAR1();

                {
                    int b = sub * 16 + bl;
                    int h = hb + j;
                    float gi = 0.f, gf = 0.f, gg = 0.f, go = 0.f;
#pragma unroll
                    for (int g4 = 0; g4 < 4; g4++) {
                        const float* gr = &Gt[(g4 * 16 + bl) * 68];
                        gi += gr[j];
                        gf += gr[16 + j];
                        gg += gr[32 + j];
                        go += gr[48 + j];
                    }
                    const __half* gx = &gxs[b * 72];
                    gi += __half2float(gx[j]);
                    gf += __half2float(gx[16 + j]);
                    gg += __half2float(gx[32 + j]);
                    go += __half2float(gx[48 + j]);

                    float si = fsig(gi);
                    float sf = fsig(gf);
                    float so = fsig(go);
                    float tg = ftanh(gg);

                    float cn = sf * cv[sub] + si * tg;
                    cv[sub] = cn;
                    float hn = so * ftanh(cn);
                    g_h_half[par ^ 1][dir][b * Hsz + h] = __float2half_rn(hn);
                    out[((size_t)b * Tlen + s) * (2 * Hsz) + dir * Hsz + h] = hn;
                    if (s == Tlen - 1) {
                        g_hT[dir][b * Hsz + h] = hn;
                        g_cT[dir][b * Hsz + h] = cn;
                    }
                }
                BAR1();

                if (tid == 0) {
                    asm volatile("fence.proxy.async;" ::: "memory");
                    unsigned* fl = &g_flags[((dir * 4 + sub) * 64 + slice) * 8];
                    asm volatile("st.release.gpu.u32 [%0], %1;"
                                 :: "l"(fl), "r"((unsigned)(s + 1)) : "memory");
                }
            }
        }
    } else {
        for (int s = 0; s < Tlen; s++) {
            const __half* Ht = g_h_half[s & 1][dir];
            for (int c = 0; c < 4; c++) {
                const int b  = c & 1;
                const int fb = s * 2 + (c >> 1);
                if (fb >= 1) mbar_wait(b ? mbC1 : mbC0, (fb - 1) & 1);
                if (s > 0) {
                    const unsigned tgt = (unsigned)s;
                    const unsigned* p0 = &g_flags[((dir * 4 + c) * 64 + lane) * 8];
                    const unsigned* p1 = &g_flags[((dir * 4 + c) * 64 + 32 + lane) * 8];
                    unsigned v0, v1;
                    do {
                        asm volatile("ld.acquire.gpu.u32 %0, [%1];" : "=r"(v0) : "l"(p0) : "memory");
                        asm volatile("ld.acquire.gpu.u32 %0, [%1];" : "=r"(v1) : "l"(p1) : "memory");
                    } while (v0 < tgt || v1 < tgt);
                    __syncwarp();
                }
                if (lane == 0) {
                    asm volatile("fence.acq_rel.gpu;" ::: "memory");
                    uint32_t mb  = b ? mbF1 : mbF0;
                    uint32_t dst = b ? hbu1 : hbu0;
                    mbar_expect(mb, 32768u);
#pragma unroll
                    for (int r = 0; r < 16; r++)
                        bulk_g2s(dst + r * WROWB, Ht + (size_t)(c * 16 + r) * Hsz, 2048u, mb);
                }
            }
        }
    }
}

// ---------------------------------------------------------------------------
// Phase 3: decoder-init projections
// ---------------------------------------------------------------------------
__global__ __launch_bounds__(128) void proj_kernel(
    const float* __restrict__ fhW, const float* __restrict__ fhb,
    const float* __restrict__ fcW, const float* __restrict__ fcb,
    float* __restrict__ out2)
{
    __shared__ float As[64][17];
    __shared__ float Bs[64][17];

    const int which = blockIdx.y;
    const float* __restrict__ W    = which ? fcW : fhW;
    const float* __restrict__ bias = which ? fcb : fhb;
    const float* __restrict__ src0 = which ? g_cT[0] : g_hT[0];
    const float* __restrict__ src1 = which ? g_cT[1] : g_hT[1];

    const int d0  = blockIdx.x * 64;
    const int tid = threadIdx.x;
    const int ty  = tid >> 4;
    const int tx  = tid & 15;

    float acc[8][4];
#pragma unroll
    for (int r = 0; r < 8; r++)
#pragma unroll
        for (int c = 0; c < 4; c++) acc[r][c] = 0.f;

    for (int k0 = 0; k0 < 2 * Hsz; k0 += 16) {
#pragma unroll
        for (int i = 0; i < 2; i++) {
            int idx = tid * 2 + i;
            int row = idx >> 2;
            int c4  = (idx & 3) << 2;
            int k   = k0 + c4;
            const float* sp = (k < Hsz) ? &src0[row * Hsz + k]
                                        : &src1[row * Hsz + k - Hsz];
            float4 v = *(const float4*)sp;
            As[row][c4 + 0] = v.x; As[row][c4 + 1] = v.y;
            As[row][c4 + 2] = v.z; As[row][c4 + 3] = v.w;

            float4 w = *(const float4*)&W[(size_t)(d0 + row) * (2 * Hsz) + k0 + c4];
            Bs[row][c4 + 0] = w.x; Bs[row][c4 + 1] = w.y;
            Bs[row][c4 + 2] = w.z; Bs[row][c4 + 3] = w.w;
        }
        __syncthreads();
#pragma unroll
        for (int kk = 0; kk < 16; kk++) {
            float a[8], b[4];
#pragma unroll
            for (int r = 0; r < 8; r++) a[r] = As[ty * 8 + r][kk];
#pragma unroll
            for (int c = 0; c < 4; c++) b[c] = Bs[tx + 16 * c][kk];
#pragma unroll
            for (int r = 0; r < 8; r++)
#pragma unroll
                for (int c = 0; c < 4; c++) acc[r][c] += a[r] * b[c];
        }
        __syncthreads();
    }

#pragma unroll
    for (int c = 0; c < 4; c++) {
        int d = d0 + tx + 16 * c;
        float bv = bias[d];
#pragma unroll
        for (int r = 0; r < 8; r++) {
            int b = ty * 8 + r;
            out2[(size_t)which * (Bsz * Hsz) + b * Hsz + d] = tanhf(acc[r][c] + bv);
        }
    }
}

// ---------------------------------------------------------------------------
// Launch
// ---------------------------------------------------------------------------
extern "C" void kernel_launch(void* const* d_in, const int* in_sizes, int n_in,
                              void* d_out, int out_size)
{
    const float* X    = (const float*)d_in[0];
    const float* Wihf = (const float*)d_in[1];
    const float* Whhf = (const float*)d_in[2];
    const float* bihf = (const float*)d_in[3];
    const float* bhhf = (const float*)d_in[4];
    const float* Wihb = (const float*)d_in[5];
    const float* Whhb = (const float*)d_in[6];
    const float* bihb = (const float*)d_in[7];
    const float* bhhb = (const float*)d_in[8];
    const float* fcW  = (const float*)d_in[9];
    const float* fcb  = (const float*)d_in[10];
    const float* fhW  = (const float*)d_in[11];
    const float* fhb  = (const float*)d_in[12];
    float* out = (float*)d_out;

    cudaFuncSetAttribute(gemm_x_mma,
                         cudaFuncAttributeMaxDynamicSharedMemorySize, P1DYN);
    cudaFuncSetAttribute(lstm_persist,
                         cudaFuncAttributeMaxDynamicSharedMemorySize, P2DYN);

    // convert also zeroes h-state and flags (fused; runs before all users)
    convert_kernel<<<(unsigned)(NCVT / 8 / 256), 256>>>(X, Wihf, Wihb, Whhf, Whhb);

    gemm_x_mma<<<dim3(NTOT / 128, MROWS / 256), 512, P1DYN>>>(bihf, bhhf, bihb, bhhb);

    lstm_persist<<<128, 288, P2DYN>>>(out);

    proj_kernel<<<dim3(Hsz / 64, 2), 128>>>(
        fhW, fhb, fcW, fcb, out + (size_t)Bsz * Tlen * 2 * Hsz);
}